// round 15
// baseline (speedup 1.0000x reference)
#include <cuda_runtime.h>
#include <cuda_bf16.h>

#define BATCH 8
#define SEQ   2048
#define DIM   512
#define DKK   64
#define SP    40    // smem pitch (bf16) for 32-wide k tiles
#define SPK   72    // pitch for 64-wide k tiles (144B = 9*16B, LDSM conflict-free)
#define TPITCH 136  // transpose smem pitch (272B, uint4-aligned)
#define BM    64    // q rows per block (fused_attn)
#define BS    64    // s chunk (double-buffered)

// ------------------------- device scratch (module-load allocated) ----------
__device__ __nv_bfloat16 g_Qh[BATCH * SEQ * DKK];
__device__ __nv_bfloat16 g_Ql[BATCH * SEQ * DKK];
__device__ __nv_bfloat16 g_Kh[BATCH * SEQ * DKK];
__device__ __nv_bfloat16 g_Kl[BATCH * SEQ * DKK];
__device__ __nv_bfloat16 g_Vth[BATCH * DKK * SEQ];   // V transposed [b][n][s]
__device__ __nv_bfloat16 g_Vtl[BATCH * DKK * SEQ];
__device__ float g_inv[BATCH * SEQ];                 // 1/rowsum

// ------------------------- helpers -----------------------------------------
__device__ __forceinline__ void split2(float x0, float x1, unsigned &h, unsigned &l) {
    __nv_bfloat16 h0 = __float2bfloat16(x0);
    __nv_bfloat16 h1 = __float2bfloat16(x1);
    float r0 = x0 - __bfloat162float(h0);
    float r1 = x1 - __bfloat162float(h1);
    __nv_bfloat162 hv; hv.x = h0; hv.y = h1;
    __nv_bfloat162 lv; lv.x = __float2bfloat16(r0); lv.y = __float2bfloat16(r1);
    h = *reinterpret_cast<unsigned*>(&hv);
    l = *reinterpret_cast<unsigned*>(&lv);
}

__device__ __forceinline__ void mma16816(float* d, const unsigned* a, const unsigned* b) {
    asm volatile(
        "mma.sync.aligned.m16n8k16.row.col.f32.bf16.bf16.f32 "
        "{%0,%1,%2,%3},{%4,%5,%6,%7},{%8,%9},{%0,%1,%2,%3};"
        : "+f"(d[0]), "+f"(d[1]), "+f"(d[2]), "+f"(d[3])
        : "r"(a[0]), "r"(a[1]), "r"(a[2]), "r"(a[3]), "r"(b[0]), "r"(b[1]));
}

__device__ __forceinline__ void ldsm4(unsigned* r, const __nv_bfloat16* p) {
    unsigned a = (unsigned)__cvta_generic_to_shared(p);
    asm volatile("ldmatrix.sync.aligned.m8n8.x4.shared.b16 {%0,%1,%2,%3}, [%4];"
                 : "=r"(r[0]), "=r"(r[1]), "=r"(r[2]), "=r"(r[3]) : "r"(a));
}

__device__ __forceinline__ void cp16(__nv_bfloat16* smem, const __nv_bfloat16* gmem) {
    unsigned s = (unsigned)__cvta_generic_to_shared(smem);
    asm volatile("cp.async.cg.shared.global [%0], [%1], 16;" :: "r"(s), "l"(gmem));
}
#define CP_COMMIT() asm volatile("cp.async.commit_group;")
#define CP_WAIT(n)  asm volatile("cp.async.wait_group %0;" :: "n"(n))
#define BAR_PAIR(id) asm volatile("bar.sync %0, 64;" :: "r"(id) : "memory")

// ---------------------------------------------------------------------------
// Kernel 1: QKV projection (exact R11 version).
// ---------------------------------------------------------------------------
__global__ void __launch_bounds__(256) qkv_mma(const float* __restrict__ in,
                                               const float* __restrict__ Wq,
                                               const float* __restrict__ Wk,
                                               const float* __restrict__ Wv) {
    extern __shared__ __nv_bfloat16 dynsm[];
    __nv_bfloat16* sAh = dynsm;
    __nv_bfloat16* sAl = dynsm + 5120;
    __nv_bfloat16* sBh = dynsm + 10240;
    __nv_bfloat16* sBl = dynsm + 12800;

    const int m0    = blockIdx.x * 128;
    const int which = blockIdx.y;
    const float* W = (which == 0) ? Wq : (which == 1) ? Wk : Wv;

    const int tid = threadIdx.x, lane = tid & 31, warp = tid >> 5;
    const int wr = warp >> 1, wc = warp & 1;
    const int gid = lane >> 2, tig = lane & 3;

    float acc[2][4][4] = {};

    for (int kc = 0; kc < 16; kc++) {
        const int k0 = kc * 32;
#pragma unroll
        for (int j = 0; j < 4; j++) {
            int idx = tid + j * 256;
            int r = idx >> 3, seg = idx & 7;
            float4 f = *(const float4*)&in[(size_t)(m0 + r) * DIM + k0 + seg * 4];
            unsigned h0, l0, h1, l1;
            split2(f.x, f.y, h0, l0);
            split2(f.z, f.w, h1, l1);
            *(unsigned*)&sAh[r * SP + seg * 4]     = h0;
            *(unsigned*)&sAh[r * SP + seg * 4 + 2] = h1;
            *(unsigned*)&sAl[r * SP + seg * 4]     = l0;
            *(unsigned*)&sAl[r * SP + seg * 4 + 2] = l1;
        }
#pragma unroll
        for (int j = 0; j < 8; j++) {
            int idx = tid + j * 256;
            int kk = idx >> 6, n = idx & 63;
            float v = W[(size_t)(k0 + kk) * DKK + n];
            __nv_bfloat16 h = __float2bfloat16(v);
            __nv_bfloat16 l = __float2bfloat16(v - __bfloat162float(h));
            sBh[n * SP + kk] = h;
            sBl[n * SP + kk] = l;
        }
        __syncthreads();

#pragma unroll
        for (int ks = 0; ks < 2; ks++) {
            const int kk = ks * 16;
            unsigned bh[4][2], bl[4][2];
#pragma unroll
            for (int nt = 0; nt < 4; nt++) {
                int n = wc * 32 + nt * 8 + gid;
                bh[nt][0] = *(unsigned*)&sBh[n * SP + kk + tig * 2];
                bh[nt][1] = *(unsigned*)&sBh[n * SP + kk + 8 + tig * 2];
                bl[nt][0] = *(unsigned*)&sBl[n * SP + kk + tig * 2];
                bl[nt][1] = *(unsigned*)&sBl[n * SP + kk + 8 + tig * 2];
            }
#pragma unroll
            for (int mt = 0; mt < 2; mt++) {
                int m = wr * 32 + mt * 16;
                unsigned ah[4], al[4];
                ah[0] = *(unsigned*)&sAh[(m + gid) * SP + kk + tig * 2];
                ah[1] = *(unsigned*)&sAh[(m + gid + 8) * SP + kk + tig * 2];
                ah[2] = *(unsigned*)&sAh[(m + gid) * SP + kk + 8 + tig * 2];
                ah[3] = *(unsigned*)&sAh[(m + gid + 8) * SP + kk + 8 + tig * 2];
                al[0] = *(unsigned*)&sAl[(m + gid) * SP + kk + tig * 2];
                al[1] = *(unsigned*)&sAl[(m + gid + 8) * SP + kk + tig * 2];
                al[2] = *(unsigned*)&sAl[(m + gid) * SP + kk + 8 + tig * 2];
                al[3] = *(unsigned*)&sAl[(m + gid + 8) * SP + kk + 8 + tig * 2];
#pragma unroll
                for (int nt = 0; nt < 4; nt++) {
                    mma16816(acc[mt][nt], ah, bh[nt]);
                    mma16816(acc[mt][nt], ah, bl[nt]);
                    mma16816(acc[mt][nt], al, bh[nt]);
                }
            }
        }
        __syncthreads();
    }

    if (which < 2) {
        __nv_bfloat16* oh = (which == 0) ? g_Qh : g_Kh;
        __nv_bfloat16* ol = (which == 0) ? g_Ql : g_Kl;
#pragma unroll
        for (int mt = 0; mt < 2; mt++)
#pragma unroll
            for (int nt = 0; nt < 4; nt++) {
                int row = m0 + wr * 32 + mt * 16 + gid;
                int col = wc * 32 + nt * 8 + tig * 2;
                size_t o = (size_t)row * DKK + col;
                unsigned h, l;
                split2(acc[mt][nt][0], acc[mt][nt][1], h, l);
                *reinterpret_cast<unsigned*>(&oh[o]) = h;
                *reinterpret_cast<unsigned*>(&ol[o]) = l;
                split2(acc[mt][nt][2], acc[mt][nt][3], h, l);
                *reinterpret_cast<unsigned*>(&oh[o + (size_t)8 * DKK]) = h;
                *reinterpret_cast<unsigned*>(&ol[o + (size_t)8 * DKK]) = l;
            }
    } else {
        __nv_bfloat16* sTh = dynsm;
        __nv_bfloat16* sTl = dynsm + 8704;
#pragma unroll
        for (int mt = 0; mt < 2; mt++)
#pragma unroll
            for (int nt = 0; nt < 4; nt++)
#pragma unroll
                for (int j = 0; j < 4; j++) {
                    int srow = wr * 32 + mt * 16 + gid + ((j >> 1) << 3);
                    int n    = wc * 32 + nt * 8 + tig * 2 + (j & 1);
                    float v = acc[mt][nt][j];
                    __nv_bfloat16 h = __float2bfloat16(v);
                    sTh[n * TPITCH + srow] = h;
                    sTl[n * TPITCH + srow] = __float2bfloat16(v - __bfloat162float(h));
                }
        __syncthreads();
        const int bb = m0 >> 11, sv = m0 & (SEQ - 1);
        const size_t base = (size_t)bb * DKK * SEQ + sv;
#pragma unroll
        for (int j = 0; j < 4; j++) {
            int idx = tid + j * 256;
            int n = idx >> 4, k8 = idx & 15;
            size_t o = base + (size_t)n * SEQ + k8 * 8;
            *(uint4*)&g_Vth[o] = *(uint4*)&sTh[n * TPITCH + k8 * 8];
            *(uint4*)&g_Vtl[o] = *(uint4*)&sTl[n * TPITCH + k8 * 8];
        }
    }
}

// ---------------------------------------------------------------------------
// Kernel 2: fused flash-style attention. Dedicated P buffer.
// Per iteration: S1 (top full sync), BAR_PAIR before MMA2, S4 (bottom full
// sync, guards K/V double-buffer overwrite by next iteration's cp.async).
// smem (bf16 elems, pitch SPK=72):
//   Qh 0      Ql 4608
//   Kh0 9216  Kl0 13824  Kh1 18432  Kl1 23040
//   Vh0 27648 Vl0 32256  Vh1 36864  Vl1 41472
//   Ph 46080  Pl 50688
//   rsum @ 55296 (64 floats)    -> 110848 bytes total
// ---------------------------------------------------------------------------
__global__ void __launch_bounds__(256, 2) fused_attn(float* __restrict__ weights,
                                                     float* __restrict__ attended) {
    extern __shared__ __nv_bfloat16 sm[];
    __nv_bfloat16* sQh = sm;
    __nv_bfloat16* sQl = sm + 4608;
    __nv_bfloat16* sKh[2] = { sm + 9216,  sm + 18432 };
    __nv_bfloat16* sKl[2] = { sm + 13824, sm + 23040 };
    __nv_bfloat16* sVh[2] = { sm + 27648, sm + 36864 };
    __nv_bfloat16* sVl[2] = { sm + 32256, sm + 41472 };
    __nv_bfloat16* sPh = sm + 46080;
    __nv_bfloat16* sPl = sm + 50688;
    float* rsum = (float*)(sm + 55296);

    const int b  = blockIdx.y;
    const int m0 = blockIdx.x * BM;
    const __nv_bfloat16* qh  = g_Qh  + (size_t)b * SEQ * DKK;
    const __nv_bfloat16* ql  = g_Ql  + (size_t)b * SEQ * DKK;
    const __nv_bfloat16* kh  = g_Kh  + (size_t)b * SEQ * DKK;
    const __nv_bfloat16* kl  = g_Kl  + (size_t)b * SEQ * DKK;
    const __nv_bfloat16* vth = g_Vth + (size_t)b * DKK * SEQ;
    const __nv_bfloat16* vtl = g_Vtl + (size_t)b * DKK * SEQ;
    float* outb = weights + (size_t)b * SEQ * SEQ;

    const int tid = threadIdx.x, lane = tid & 31, warp = tid >> 5;
    const int wr = warp >> 1, wc = warp & 1;        // 4 m-warps x 2 n-warps
    const int gid = lane >> 2, tig = lane & 3;
    const int m = wr * 16;
    const int barid = wr + 1;                       // named barrier per m-pair

    const int lr = lane & 15;
    const int lh = lane >> 4;
    const int br = ((lane >> 4) << 3) + (lane & 7);
    const int bc = ((lane >> 3) & 1) * 8;

    // stage Q once (64 x 64, both planes)
#pragma unroll
    for (int j = 0; j < 2; j++) {
        int idx = tid + j * 256;
        int r = idx >> 3, c8 = idx & 7;
        *(uint4*)&sQh[r * SPK + c8 * 8] = *(const uint4*)&qh[(size_t)(m0 + r) * DKK + c8 * 8];
        *(uint4*)&sQl[r * SPK + c8 * 8] = *(const uint4*)&ql[(size_t)(m0 + r) * DKK + c8 * 8];
    }
    if (tid < 64) rsum[tid] = 0.f;

    auto stage_kv = [&](int s0, int bu) {
#pragma unroll
        for (int j = 0; j < 4; j++) {
            int idx = tid + j * 256;
            int pl = idx >> 9, r = (idx >> 3) & 63, c8 = idx & 7;
            const __nv_bfloat16* src = (pl ? kl : kh) + (size_t)(s0 + r) * DKK + c8 * 8;
            __nv_bfloat16* dst = (pl ? sKl[bu] : sKh[bu]) + r * SPK + c8 * 8;
            cp16(dst, src);
        }
#pragma unroll
        for (int j = 0; j < 4; j++) {
            int idx = tid + j * 256;
            int pl = idx >> 9, n = (idx >> 3) & 63, c8 = idx & 7;
            const __nv_bfloat16* src = (pl ? vtl : vth) + (size_t)n * SEQ + s0 + c8 * 8;
            __nv_bfloat16* dst = (pl ? sVl[bu] : sVh[bu]) + n * SPK + c8 * 8;
            cp16(dst, src);
        }
        CP_COMMIT();
    };

    stage_kv(0, 0);

    float rs0 = 0.f, rs1 = 0.f;
    float acc2[4][4] = {};

    const int NIT = SEQ / BS;                         // 32
    for (int it = 0; it < NIT; it++) {
        const int s0 = it * BS;
        const int bu = it & 1;

        if (it + 1 < NIT) {
            stage_kv(s0 + BS, bu ^ 1);                // safe: S4 of it-1 passed
            CP_WAIT(1);                               // chunk it resident
        } else {
            CP_WAIT(0);
        }
        __syncthreads();                              // S1: chunk it visible

        // ---- MMA1: C1[64 x 64] = Q . K^T ----
        float acc1[4][4] = {};
#pragma unroll
        for (int ks = 0; ks < 4; ks++) {
            const int kk = ks * 16;
            unsigned ah[4], al[4];
            ldsm4(ah, &sQh[(m + lr) * SPK + kk + lh * 8]);
            ldsm4(al, &sQl[(m + lr) * SPK + kk + lh * 8]);
#pragma unroll
            for (int np = 0; np < 2; np++) {
                int nb = wc * 32 + np * 16;
                unsigned bh[4], bl[4];
                ldsm4(bh, &sKh[bu][(nb + br) * SPK + kk + bc]);
                ldsm4(bl, &sKl[bu][(nb + br) * SPK + kk + bc]);
                mma16816(acc1[np * 2],     ah, bh);
                mma16816(acc1[np * 2],     ah, bl);
                mma16816(acc1[np * 2],     al, bh);
                mma16816(acc1[np * 2 + 1], ah, bh + 2);
                mma16816(acc1[np * 2 + 1], ah, bl + 2);
                mma16816(acc1[np * 2 + 1], al, bh + 2);
            }
        }
        // no block sync: P is a dedicated buffer, K untouched

        // ---- exp, rowsum, write unnormalized weights, store P ----
        const int r0 = m0 + m + gid, r1 = r0 + 8;
#pragma unroll
        for (int nt = 0; nt < 4; nt++) {
            int col = wc * 32 + nt * 8 + tig * 2;
            float e0 = __expf(acc1[nt][0] * 0.125f);
            float e1 = __expf(acc1[nt][1] * 0.125f);
            float e2 = __expf(acc1[nt][2] * 0.125f);
            float e3 = __expf(acc1[nt][3] * 0.125f);
            rs0 += e0 + e1;
            rs1 += e2 + e3;
            float2 w0 = {e0, e1}, w1 = {e2, e3};
            *(float2*)&outb[(size_t)r0 * SEQ + s0 + col] = w0;
            *(float2*)&outb[(size_t)r1 * SEQ + s0 + col] = w1;
            unsigned h, l;
            split2(e0, e1, h, l);
            *(unsigned*)&sPh[(m + gid) * SPK + col] = h;
            *(unsigned*)&sPl[(m + gid) * SPK + col] = l;
            split2(e2, e3, h, l);
            *(unsigned*)&sPh[(m + gid + 8) * SPK + col] = h;
            *(unsigned*)&sPl[(m + gid + 8) * SPK + col] = l;
        }
        BAR_PAIR(barid);          // pair's 64-col P rows m..m+15 complete

        // ---- MMA2: attended[64 x 64] += P . V^T ----
#pragma unroll
        for (int ks = 0; ks < 4; ks++) {
            const int kk = ks * 16;
            unsigned ah[4], al[4];
            ldsm4(ah, &sPh[(m + lr) * SPK + kk + lh * 8]);
            ldsm4(al, &sPl[(m + lr) * SPK + kk + lh * 8]);
#pragma unroll
            for (int np = 0; np < 2; np++) {
                int nb = wc * 32 + np * 16;
                unsigned bh[4], bl[4];
                ldsm4(bh, &sVh[bu][(nb + br) * SPK + kk + bc]);
                ldsm4(bl, &sVl[bu][(nb + br) * SPK + kk + bc]);
                mma16816(acc2[np * 2],     ah, bh);
                mma16816(acc2[np * 2],     ah, bl);
                mma16816(acc2[np * 2],     al, bh);
                mma16816(acc2[np * 2 + 1], ah, bh + 2);
                mma16816(acc2[np * 2 + 1], ah, bl + 2);
                mma16816(acc2[np * 2 + 1], al, bh + 2);
            }
        }
        __syncthreads();          // S4: all reads of K/V[bu] done before the
                                  // next iteration's cp.async overwrites bu^1
                                  // (issued only after every warp passes here)
    }

    // ---- rowsum reduce ----
    rs0 += __shfl_xor_sync(0xffffffffu, rs0, 1);
    rs0 += __shfl_xor_sync(0xffffffffu, rs0, 2);
    rs1 += __shfl_xor_sync(0xffffffffu, rs1, 1);
    rs1 += __shfl_xor_sync(0xffffffffu, rs1, 2);
    if (tig == 0) {
        atomicAdd(&rsum[m + gid], rs0);        // exactly 2 contributors
        atomicAdd(&rsum[m + gid + 8], rs1);
    }
    __syncthreads();

    if (tid < 64)
        g_inv[b * SEQ + m0 + tid] = 1.0f / rsum[tid];

    const int rr0 = m + gid, rr1 = rr0 + 8;
    const float iv0 = 1.0f / rsum[rr0];
    const float iv1 = 1.0f / rsum[rr1];
#pragma unroll
    for (int nt = 0; nt < 4; nt++) {
        int col = wc * 32 + nt * 8 + tig * 2;
        float2 v0 = { acc2[nt][0] * iv0, acc2[nt][1] * iv0 };
        float2 v1 = { acc2[nt][2] * iv1, acc2[nt][3] * iv1 };
        *(float2*)&attended[((size_t)b * SEQ + m0 + rr0) * DKK + col] = v0;
        *(float2*)&attended[((size_t)b * SEQ + m0 + rr1) * DKK + col] = v1;
    }
}

// ---------------------------------------------------------------------------
// Kernel 3: streaming normalize of weights (BW-bound, unchanged)
// ---------------------------------------------------------------------------
__global__ void __launch_bounds__(256) norm_weights(float* __restrict__ weights) {
    const int row = blockIdx.x;
    const float iv = g_inv[row];
    float4* w = (float4*)(weights + (size_t)row * SEQ);
    const int tid = threadIdx.x;
#pragma unroll
    for (int j = 0; j < 2; j++) {
        int i = tid + j * 256;
        float4 f = w[i];
        f.x *= iv; f.y *= iv; f.z *= iv; f.w *= iv;
        w[i] = f;
    }
}

// ---------------------------------------------------------------------------
extern "C" void kernel_launch(void* const* d_in, const int* in_sizes, int n_in,
                              void* d_out, int out_size) {
    const float* in = (const float*)d_in[0];
    const float* Wq = (const float*)d_in[1];
    const float* Wk = (const float*)d_in[2];
    const float* Wv = (const float*)d_in[3];

    float* out      = (float*)d_out;
    float* attended = out;                               // [B,S,DK]
    float* weights  = out + (size_t)BATCH * SEQ * DKK;   // [B,S,S]

    const int QKV_SMEM   = 17408 * 2;                    // 34816
    const int SMEM_BYTES = 55296 * 2 + 64 * 4;           // 110848
    cudaFuncSetAttribute(fused_attn, cudaFuncAttributeMaxDynamicSharedMemorySize, SMEM_BYTES);

    // 1) QKV projection (V written transposed via smem)
    dim3 g1(SEQ * BATCH / 128, 3);
    qkv_mma<<<g1, 256, QKV_SMEM>>>(in, Wq, Wk, Wv);

    // 2) fused attention: unnormalized weights + normalized attended + g_inv
    dim3 g2(SEQ / BM, BATCH);
    fused_attn<<<g2, 256, SMEM_BYTES>>>(weights, attended);

    // 3) normalize weights in place
    norm_weights<<<BATCH * SEQ, 256>>>(weights);
}

// round 16
// speedup vs baseline: 1.0252x; 1.0252x over previous
#include <cuda_runtime.h>
#include <cuda_bf16.h>

#define BATCH 8
#define SEQ   2048
#define DIM   512
#define DKK   64
#define SP    40    // smem pitch (bf16) for 32-wide k tiles
#define SPK   72    // pitch for 64-wide k tiles (144B = 9*16B, LDSM conflict-free)
#define TPITCH 136  // transpose smem pitch (272B, uint4-aligned)
#define BM    64    // q rows per block (fused_attn)
#define BS    64    // s chunk (double-buffered)

// ------------------------- device scratch (module-load allocated) ----------
__device__ __nv_bfloat16 g_Qh[BATCH * SEQ * DKK];
__device__ __nv_bfloat16 g_Ql[BATCH * SEQ * DKK];
__device__ __nv_bfloat16 g_Kh[BATCH * SEQ * DKK];
__device__ __nv_bfloat16 g_Kl[BATCH * SEQ * DKK];
__device__ __nv_bfloat16 g_Vth[BATCH * DKK * SEQ];   // V transposed [b][n][s]
__device__ __nv_bfloat16 g_Vtl[BATCH * DKK * SEQ];
__device__ __nv_bfloat16 g_Wth[3 * DKK * DIM];       // W transposed split [which][n][k]
__device__ __nv_bfloat16 g_Wtl[3 * DKK * DIM];
__device__ float g_inv[BATCH * SEQ];                 // 1/rowsum

// ------------------------- helpers -----------------------------------------
__device__ __forceinline__ void split2(float x0, float x1, unsigned &h, unsigned &l) {
    __nv_bfloat16 h0 = __float2bfloat16(x0);
    __nv_bfloat16 h1 = __float2bfloat16(x1);
    float r0 = x0 - __bfloat162float(h0);
    float r1 = x1 - __bfloat162float(h1);
    __nv_bfloat162 hv; hv.x = h0; hv.y = h1;
    __nv_bfloat162 lv; lv.x = __float2bfloat16(r0); lv.y = __float2bfloat16(r1);
    h = *reinterpret_cast<unsigned*>(&hv);
    l = *reinterpret_cast<unsigned*>(&lv);
}

__device__ __forceinline__ void mma16816(float* d, const unsigned* a, const unsigned* b) {
    asm volatile(
        "mma.sync.aligned.m16n8k16.row.col.f32.bf16.bf16.f32 "
        "{%0,%1,%2,%3},{%4,%5,%6,%7},{%8,%9},{%0,%1,%2,%3};"
        : "+f"(d[0]), "+f"(d[1]), "+f"(d[2]), "+f"(d[3])
        : "r"(a[0]), "r"(a[1]), "r"(a[2]), "r"(a[3]), "r"(b[0]), "r"(b[1]));
}

__device__ __forceinline__ void ldsm4(unsigned* r, const __nv_bfloat16* p) {
    unsigned a = (unsigned)__cvta_generic_to_shared(p);
    asm volatile("ldmatrix.sync.aligned.m8n8.x4.shared.b16 {%0,%1,%2,%3}, [%4];"
                 : "=r"(r[0]), "=r"(r[1]), "=r"(r[2]), "=r"(r[3]) : "r"(a));
}

__device__ __forceinline__ void cp16(__nv_bfloat16* smem, const __nv_bfloat16* gmem) {
    unsigned s = (unsigned)__cvta_generic_to_shared(smem);
    asm volatile("cp.async.cg.shared.global [%0], [%1], 16;" :: "r"(s), "l"(gmem));
}
#define CP_COMMIT() asm volatile("cp.async.commit_group;")
#define CP_WAIT(n)  asm volatile("cp.async.wait_group %0;" :: "n"(n))

// ---------------------------------------------------------------------------
// Kernel 0: pre-split weights into transposed bf16 planes g_Wt*[which][n][k].
// grid (DIM/64, 3), 256 threads.  (validated in R13)
// ---------------------------------------------------------------------------
__global__ void __launch_bounds__(256) wsplit(const float* __restrict__ Wq,
                                              const float* __restrict__ Wk,
                                              const float* __restrict__ Wv) {
    __shared__ float st[64][65];
    const int which = blockIdx.y;
    const int k0 = blockIdx.x * 64;
    const float* W = (which == 0) ? Wq : (which == 1) ? Wk : Wv;
    const int tid = threadIdx.x;

#pragma unroll
    for (int j = 0; j < 16; j++) {
        int idx = tid + j * 256;              // 0..4095
        int kk = idx >> 6, n = idx & 63;
        st[kk][n] = W[(size_t)(k0 + kk) * DKK + n];
    }
    __syncthreads();
#pragma unroll
    for (int j = 0; j < 16; j++) {
        int idx = tid + j * 256;
        int n = idx >> 6, kk = idx & 63;
        float v = st[kk][n];
        __nv_bfloat16 h = __float2bfloat16(v);
        size_t o = (size_t)which * DKK * DIM + (size_t)n * DIM + k0 + kk;
        g_Wth[o] = h;
        g_Wtl[o] = __float2bfloat16(v - __bfloat162float(h));
    }
}

// ---------------------------------------------------------------------------
// Kernel 1: QKV projection (R11 structure; B staged from pre-split planes).
// ---------------------------------------------------------------------------
__global__ void __launch_bounds__(256) qkv_mma(const float* __restrict__ in) {
    extern __shared__ __nv_bfloat16 dynsm[];
    __nv_bfloat16* sAh = dynsm;
    __nv_bfloat16* sAl = dynsm + 5120;
    __nv_bfloat16* sBh = dynsm + 10240;
    __nv_bfloat16* sBl = dynsm + 12800;

    const int m0    = blockIdx.x * 128;
    const int which = blockIdx.y;
    const __nv_bfloat16* wth = g_Wth + (size_t)which * DKK * DIM;
    const __nv_bfloat16* wtl = g_Wtl + (size_t)which * DKK * DIM;

    const int tid = threadIdx.x, lane = tid & 31, warp = tid >> 5;
    const int wr = warp >> 1, wc = warp & 1;
    const int gid = lane >> 2, tig = lane & 3;

    float acc[2][4][4] = {};

    for (int kc = 0; kc < 16; kc++) {
        const int k0 = kc * 32;
        // stage A: 128 rows x 32 k fp32 -> split planes
#pragma unroll
        for (int j = 0; j < 4; j++) {
            int idx = tid + j * 256;
            int r = idx >> 3, seg = idx & 7;
            float4 f = *(const float4*)&in[(size_t)(m0 + r) * DIM + k0 + seg * 4];
            unsigned h0, l0, h1, l1;
            split2(f.x, f.y, h0, l0);
            split2(f.z, f.w, h1, l1);
            *(unsigned*)&sAh[r * SP + seg * 4]     = h0;
            *(unsigned*)&sAh[r * SP + seg * 4 + 2] = h1;
            *(unsigned*)&sAl[r * SP + seg * 4]     = l0;
            *(unsigned*)&sAl[r * SP + seg * 4 + 2] = l1;
        }
        // stage B: 64 n-rows x 32 k from pre-split planes (pure uint4 copies)
#pragma unroll
        for (int j = 0; j < 2; j++) {
            int idx = tid + j * 256;            // 0..511
            int pl = idx >> 8;                  // 0=h, 1=l
            int r  = (idx >> 2) & 63;           // n row
            int q4 = idx & 3;                   // 8-elem segment
            const __nv_bfloat16* src = (pl ? wtl : wth) + (size_t)r * DIM + k0 + q4 * 8;
            __nv_bfloat16* dst = (pl ? sBl : sBh) + r * SP + q4 * 8;
            *(uint4*)dst = *(const uint4*)src;
        }
        __syncthreads();

#pragma unroll
        for (int ks = 0; ks < 2; ks++) {
            const int kk = ks * 16;
            unsigned bh[4][2], bl[4][2];
#pragma unroll
            for (int nt = 0; nt < 4; nt++) {
                int n = wc * 32 + nt * 8 + gid;
                bh[nt][0] = *(unsigned*)&sBh[n * SP + kk + tig * 2];
                bh[nt][1] = *(unsigned*)&sBh[n * SP + kk + 8 + tig * 2];
                bl[nt][0] = *(unsigned*)&sBl[n * SP + kk + tig * 2];
                bl[nt][1] = *(unsigned*)&sBl[n * SP + kk + 8 + tig * 2];
            }
#pragma unroll
            for (int mt = 0; mt < 2; mt++) {
                int m = wr * 32 + mt * 16;
                unsigned ah[4], al[4];
                ah[0] = *(unsigned*)&sAh[(m + gid) * SP + kk + tig * 2];
                ah[1] = *(unsigned*)&sAh[(m + gid + 8) * SP + kk + tig * 2];
                ah[2] = *(unsigned*)&sAh[(m + gid) * SP + kk + 8 + tig * 2];
                ah[3] = *(unsigned*)&sAh[(m + gid + 8) * SP + kk + 8 + tig * 2];
                al[0] = *(unsigned*)&sAl[(m + gid) * SP + kk + tig * 2];
                al[1] = *(unsigned*)&sAl[(m + gid + 8) * SP + kk + tig * 2];
                al[2] = *(unsigned*)&sAl[(m + gid) * SP + kk + 8 + tig * 2];
                al[3] = *(unsigned*)&sAl[(m + gid + 8) * SP + kk + 8 + tig * 2];
#pragma unroll
                for (int nt = 0; nt < 4; nt++) {
                    mma16816(acc[mt][nt], ah, bh[nt]);
                    mma16816(acc[mt][nt], ah, bl[nt]);
                    mma16816(acc[mt][nt], al, bh[nt]);
                }
            }
        }
        __syncthreads();
    }

    if (which < 2) {
        __nv_bfloat16* oh = (which == 0) ? g_Qh : g_Kh;
        __nv_bfloat16* ol = (which == 0) ? g_Ql : g_Kl;
#pragma unroll
        for (int mt = 0; mt < 2; mt++)
#pragma unroll
            for (int nt = 0; nt < 4; nt++) {
                int row = m0 + wr * 32 + mt * 16 + gid;
                int col = wc * 32 + nt * 8 + tig * 2;
                size_t o = (size_t)row * DKK + col;
                unsigned h, l;
                split2(acc[mt][nt][0], acc[mt][nt][1], h, l);
                *reinterpret_cast<unsigned*>(&oh[o]) = h;
                *reinterpret_cast<unsigned*>(&ol[o]) = l;
                split2(acc[mt][nt][2], acc[mt][nt][3], h, l);
                *reinterpret_cast<unsigned*>(&oh[o + (size_t)8 * DKK]) = h;
                *reinterpret_cast<unsigned*>(&ol[o + (size_t)8 * DKK]) = l;
            }
    } else {
        // V: transpose through smem (aliases staging), coalesced uint4 stores
        __nv_bfloat16* sTh = dynsm;
        __nv_bfloat16* sTl = dynsm + 8704;
#pragma unroll
        for (int mt = 0; mt < 2; mt++)
#pragma unroll
            for (int nt = 0; nt < 4; nt++)
#pragma unroll
                for (int j = 0; j < 4; j++) {
                    int srow = wr * 32 + mt * 16 + gid + ((j >> 1) << 3);
                    int n    = wc * 32 + nt * 8 + tig * 2 + (j & 1);
                    float v = acc[mt][nt][j];
                    __nv_bfloat16 h = __float2bfloat16(v);
                    sTh[n * TPITCH + srow] = h;
                    sTl[n * TPITCH + srow] = __float2bfloat16(v - __bfloat162float(h));
                }
        __syncthreads();
        const int bb = m0 >> 11, sv = m0 & (SEQ - 1);
        const size_t base = (size_t)bb * DKK * SEQ + sv;
#pragma unroll
        for (int j = 0; j < 4; j++) {
            int idx = tid + j * 256;
            int n = idx >> 4, k8 = idx & 15;
            size_t o = base + (size_t)n * SEQ + k8 * 8;
            *(uint4*)&g_Vth[o] = *(uint4*)&sTh[n * TPITCH + k8 * 8];
            *(uint4*)&g_Vtl[o] = *(uint4*)&sTl[n * TPITCH + k8 * 8];
        }
    }
}

// ---------------------------------------------------------------------------
// Kernel 2: fused flash-style attention (exact R11/R8 version, best measured).
// ---------------------------------------------------------------------------
__global__ void __launch_bounds__(256, 2) fused_attn(float* __restrict__ weights,
                                                     float* __restrict__ attended) {
    extern __shared__ __nv_bfloat16 sm[];
    __nv_bfloat16* sQh = sm;
    __nv_bfloat16* sQl = sm + 4608;
    __nv_bfloat16* sKh[2] = { sm + 9216,  sm + 18432 };
    __nv_bfloat16* sKl[2] = { sm + 13824, sm + 23040 };
    __nv_bfloat16* sVh[2] = { sm + 27648, sm + 36864 };
    __nv_bfloat16* sVl[2] = { sm + 32256, sm + 41472 };
    float* rsum = (float*)(sm + 46080);

    const int b  = blockIdx.y;
    const int m0 = blockIdx.x * BM;
    const __nv_bfloat16* qh  = g_Qh  + (size_t)b * SEQ * DKK;
    const __nv_bfloat16* ql  = g_Ql  + (size_t)b * SEQ * DKK;
    const __nv_bfloat16* kh  = g_Kh  + (size_t)b * SEQ * DKK;
    const __nv_bfloat16* kl  = g_Kl  + (size_t)b * SEQ * DKK;
    const __nv_bfloat16* vth = g_Vth + (size_t)b * DKK * SEQ;
    const __nv_bfloat16* vtl = g_Vtl + (size_t)b * DKK * SEQ;
    float* outb = weights + (size_t)b * SEQ * SEQ;

    const int tid = threadIdx.x, lane = tid & 31, warp = tid >> 5;
    const int wr = warp >> 1, wc = warp & 1;        // 4 m-warps x 2 n-warps
    const int gid = lane >> 2, tig = lane & 3;
    const int m = wr * 16;

    const int lr = lane & 15;
    const int lh = lane >> 4;
    const int br = ((lane >> 4) << 3) + (lane & 7);
    const int bc = ((lane >> 3) & 1) * 8;

#pragma unroll
    for (int j = 0; j < 2; j++) {
        int idx = tid + j * 256;
        int r = idx >> 3, c8 = idx & 7;
        *(uint4*)&sQh[r * SPK + c8 * 8] = *(const uint4*)&qh[(size_t)(m0 + r) * DKK + c8 * 8];
        *(uint4*)&sQl[r * SPK + c8 * 8] = *(const uint4*)&ql[(size_t)(m0 + r) * DKK + c8 * 8];
    }
    if (tid < 64) rsum[tid] = 0.f;

    auto stage_kv = [&](int s0, int bu) {
#pragma unroll
        for (int j = 0; j < 4; j++) {
            int idx = tid + j * 256;
            int pl = idx >> 9, r = (idx >> 3) & 63, c8 = idx & 7;
            const __nv_bfloat16* src = (pl ? kl : kh) + (size_t)(s0 + r) * DKK + c8 * 8;
            __nv_bfloat16* dst = (pl ? sKl[bu] : sKh[bu]) + r * SPK + c8 * 8;
            cp16(dst, src);
        }
#pragma unroll
        for (int j = 0; j < 4; j++) {
            int idx = tid + j * 256;
            int pl = idx >> 9, n = (idx >> 3) & 63, c8 = idx & 7;
            const __nv_bfloat16* src = (pl ? vtl : vth) + (size_t)n * SEQ + s0 + c8 * 8;
            __nv_bfloat16* dst = (pl ? sVl[bu] : sVh[bu]) + n * SPK + c8 * 8;
            cp16(dst, src);
        }
        CP_COMMIT();
    };

    stage_kv(0, 0);

    float rs0 = 0.f, rs1 = 0.f;
    float acc2[4][4] = {};

    const int NIT = SEQ / BS;                         // 32
    for (int it = 0; it < NIT; it++) {
        const int s0 = it * BS;
        const int bu = it & 1;

        if (it + 1 < NIT) {
            stage_kv(s0 + BS, bu ^ 1);
            CP_WAIT(1);
        } else {
            CP_WAIT(0);
        }
        __syncthreads();

        // ---- MMA1: C1[64 x 64] = Q . K^T ----
        float acc1[4][4] = {};
#pragma unroll
        for (int ks = 0; ks < 4; ks++) {
            const int kk = ks * 16;
            unsigned ah[4], al[4];
            ldsm4(ah, &sQh[(m + lr) * SPK + kk + lh * 8]);
            ldsm4(al, &sQl[(m + lr) * SPK + kk + lh * 8]);
#pragma unroll
            for (int np = 0; np < 2; np++) {
                int nb = wc * 32 + np * 16;
                unsigned bh[4], bl[4];
                ldsm4(bh, &sKh[bu][(nb + br) * SPK + kk + bc]);
                ldsm4(bl, &sKl[bu][(nb + br) * SPK + kk + bc]);
                mma16816(acc1[np * 2],     ah, bh);
                mma16816(acc1[np * 2],     ah, bl);
                mma16816(acc1[np * 2],     al, bh);
                mma16816(acc1[np * 2 + 1], ah, bh + 2);
                mma16816(acc1[np * 2 + 1], ah, bl + 2);
                mma16816(acc1[np * 2 + 1], al, bh + 2);
            }
        }
        __syncthreads();

        // ---- exp, rowsum, write unnormalized weights, store P into K[bu] ----
        __nv_bfloat16* sPh = sKh[bu];
        __nv_bfloat16* sPl = sKl[bu];
        const int r0 = m0 + m + gid, r1 = r0 + 8;
#pragma unroll
        for (int nt = 0; nt < 4; nt++) {
            int col = wc * 32 + nt * 8 + tig * 2;
            float e0 = __expf(acc1[nt][0] * 0.125f);
            float e1 = __expf(acc1[nt][1] * 0.125f);
            float e2 = __expf(acc1[nt][2] * 0.125f);
            float e3 = __expf(acc1[nt][3] * 0.125f);
            rs0 += e0 + e1;
            rs1 += e2 + e3;
            float2 w0 = {e0, e1}, w1 = {e2, e3};
            *(float2*)&outb[(size_t)r0 * SEQ + s0 + col] = w0;
            *(float2*)&outb[(size_t)r1 * SEQ + s0 + col] = w1;
            unsigned h, l;
            split2(e0, e1, h, l);
            *(unsigned*)&sPh[(m + gid) * SPK + col] = h;
            *(unsigned*)&sPl[(m + gid) * SPK + col] = l;
            split2(e2, e3, h, l);
            *(unsigned*)&sPh[(m + gid + 8) * SPK + col] = h;
            *(unsigned*)&sPl[(m + gid + 8) * SPK + col] = l;
        }
        __syncthreads();

        // ---- MMA2: attended[64 x 64] += P . V^T ----
#pragma unroll
        for (int ks = 0; ks < 4; ks++) {
            const int kk = ks * 16;
            unsigned ah[4], al[4];
            ldsm4(ah, &sPh[(m + lr) * SPK + kk + lh * 8]);
            ldsm4(al, &sPl[(m + lr) * SPK + kk + lh * 8]);
#pragma unroll
            for (int np = 0; np < 2; np++) {
                int nb = wc * 32 + np * 16;
                unsigned bh[4], bl[4];
                ldsm4(bh, &sVh[bu][(nb + br) * SPK + kk + bc]);
                ldsm4(bl, &sVl[bu][(nb + br) * SPK + kk + bc]);
                mma16816(acc2[np * 2],     ah, bh);
                mma16816(acc2[np * 2],     ah, bl);
                mma16816(acc2[np * 2],     al, bh);
                mma16816(acc2[np * 2 + 1], ah, bh + 2);
                mma16816(acc2[np * 2 + 1], ah, bl + 2);
                mma16816(acc2[np * 2 + 1], al, bh + 2);
            }
        }
        __syncthreads();
    }

    // ---- rowsum reduce ----
    rs0 += __shfl_xor_sync(0xffffffffu, rs0, 1);
    rs0 += __shfl_xor_sync(0xffffffffu, rs0, 2);
    rs1 += __shfl_xor_sync(0xffffffffu, rs1, 1);
    rs1 += __shfl_xor_sync(0xffffffffu, rs1, 2);
    if (tig == 0) {
        atomicAdd(&rsum[m + gid], rs0);
        atomicAdd(&rsum[m + gid + 8], rs1);
    }
    __syncthreads();

    if (tid < 64)
        g_inv[b * SEQ + m0 + tid] = 1.0f / rsum[tid];

    const int rr0 = m + gid, rr1 = rr0 + 8;
    const float iv0 = 1.0f / rsum[rr0];
    const float iv1 = 1.0f / rsum[rr1];
#pragma unroll
    for (int nt = 0; nt < 4; nt++) {
        int col = wc * 32 + nt * 8 + tig * 2;
        float2 v0 = { acc2[nt][0] * iv0, acc2[nt][1] * iv0 };
        float2 v1 = { acc2[nt][2] * iv1, acc2[nt][3] * iv1 };
        *(float2*)&attended[((size_t)b * SEQ + m0 + rr0) * DKK + col] = v0;
        *(float2*)&attended[((size_t)b * SEQ + m0 + rr1) * DKK + col] = v1;
    }
}

// ---------------------------------------------------------------------------
// Kernel 3: streaming normalize of weights (BW-bound, unchanged)
// ---------------------------------------------------------------------------
__global__ void __launch_bounds__(256) norm_weights(float* __restrict__ weights) {
    const int row = blockIdx.x;
    const float iv = g_inv[row];
    float4* w = (float4*)(weights + (size_t)row * SEQ);
    const int tid = threadIdx.x;
#pragma unroll
    for (int j = 0; j < 2; j++) {
        int i = tid + j * 256;
        float4 f = w[i];
        f.x *= iv; f.y *= iv; f.z *= iv; f.w *= iv;
        w[i] = f;
    }
}

// ---------------------------------------------------------------------------
extern "C" void kernel_launch(void* const* d_in, const int* in_sizes, int n_in,
                              void* d_out, int out_size) {
    const float* in = (const float*)d_in[0];
    const float* Wq = (const float*)d_in[1];
    const float* Wk = (const float*)d_in[2];
    const float* Wv = (const float*)d_in[3];

    float* out      = (float*)d_out;
    float* attended = out;                               // [B,S,DK]
    float* weights  = out + (size_t)BATCH * SEQ * DKK;   // [B,S,S]

    const int QKV_SMEM   = 17408 * 2;                    // 34816
    const int SMEM_BYTES = 46080 * 2 + 64 * 4;           // 92416
    cudaFuncSetAttribute(fused_attn, cudaFuncAttributeMaxDynamicSharedMemorySize, SMEM_BYTES);

    // 0) pre-split weights (transposed bf16 planes)
    dim3 gw(DIM / 64, 3);
    wsplit<<<gw, 256>>>(Wq, Wk, Wv);

    // 1) QKV projection (B from pre-split planes; V written transposed)
    dim3 g1(SEQ * BATCH / 128, 3);
    qkv_mma<<<g1, 256, QKV_SMEM>>>(in);

    // 2) fused attention: unnormalized weights + normalized attended + g_inv
    dim3 g2(SEQ / BM, BATCH);
    fused_attn<<<g2, 256, SMEM_BYTES>>>(weights, attended);

    // 3) normalize weights in place
    norm_weights<<<BATCH * SEQ, 256>>>(weights);
}